// round 9
// baseline (speedup 1.0000x reference)
#include <cuda_runtime.h>
#include <cstdint>

// SimplifiedMambaBlock — analytical identity:
//   h0 = 0 and the scan is purely multiplicative (h = A_t * h, no input
//   injection), so h ≡ 0 → ssm_out ≡ 0 → y ≡ 0 → out = 0; reference returns
//   residual == x bit-exactly. Optimal kernel = device copy of x.
//
// R4: L2 eviction-policy experiment. Two kernels (fp4 scalar-ish and v8)
// both hit a 10.7 µs wall with nothing saturated. Hypothesis: across graph
// replays, the 33.5 MB output stream evicts x from L2, so reads go to DRAM
// every replay. Fix: ld.global with L2::evict_last on x (pin resident),
// st.global with L2::evict_first on out (stream through). MLP=4/thread.

__device__ __forceinline__ void ldg_v8_el(const unsigned* p, unsigned r[8]) {
    asm volatile("ld.global.L2::evict_last.v8.b32 {%0,%1,%2,%3,%4,%5,%6,%7}, [%8];"
                 : "=r"(r[0]), "=r"(r[1]), "=r"(r[2]), "=r"(r[3]),
                   "=r"(r[4]), "=r"(r[5]), "=r"(r[6]), "=r"(r[7])
                 : "l"(p));
}

__device__ __forceinline__ void stg_v8_ef(unsigned* p, const unsigned r[8]) {
    asm volatile("st.global.L2::evict_first.v8.b32 [%0], {%1,%2,%3,%4,%5,%6,%7,%8};"
                 :: "l"(p),
                    "r"(r[0]), "r"(r[1]), "r"(r[2]), "r"(r[3]),
                    "r"(r[4]), "r"(r[5]), "r"(r[6]), "r"(r[7])
                 : "memory");
}

// Each thread copies four 32B chunks at stride = total threads; all loads
// issued before any store (MLP=4).
__global__ void __launch_bounds__(256)
copy_v8x4(const unsigned* __restrict__ src, unsigned* __restrict__ dst,
          unsigned n_chunks)
{
    unsigned gid = blockIdx.x * 256u + threadIdx.x;
    unsigned nt = gridDim.x * 256u;

    unsigned i0 = gid;
    unsigned i1 = gid + nt;
    unsigned i2 = gid + 2u * nt;
    unsigned i3 = gid + 3u * nt;

    unsigned a[8], b[8], c[8], d[8];
    if (i3 < n_chunks) {
        ldg_v8_el(src + (size_t)i0 * 8u, a);
        ldg_v8_el(src + (size_t)i1 * 8u, b);
        ldg_v8_el(src + (size_t)i2 * 8u, c);
        ldg_v8_el(src + (size_t)i3 * 8u, d);
        stg_v8_ef(dst + (size_t)i0 * 8u, a);
        stg_v8_ef(dst + (size_t)i1 * 8u, b);
        stg_v8_ef(dst + (size_t)i2 * 8u, c);
        stg_v8_ef(dst + (size_t)i3 * 8u, d);
    } else {
        // generic guarded path (only the last partial wave takes this)
        if (i0 < n_chunks) { ldg_v8_el(src + (size_t)i0 * 8u, a); stg_v8_ef(dst + (size_t)i0 * 8u, a); }
        if (i1 < n_chunks) { ldg_v8_el(src + (size_t)i1 * 8u, b); stg_v8_ef(dst + (size_t)i1 * 8u, b); }
        if (i2 < n_chunks) { ldg_v8_el(src + (size_t)i2 * 8u, c); stg_v8_ef(dst + (size_t)i2 * 8u, c); }
    }
}

__global__ void __launch_bounds__(256)
copy_tail(const float* __restrict__ src, float* __restrict__ dst,
          unsigned start, unsigned n)
{
    unsigned i = start + blockIdx.x * 256u + threadIdx.x;
    if (i < n) dst[i] = src[i];
}

extern "C" void kernel_launch(void* const* d_in, const int* in_sizes, int n_in,
                              void* d_out, int out_size)
{
    const float* x = (const float*)d_in[0];   // metadata order: x first
    float* out = (float*)d_out;

    unsigned n = (unsigned)out_size;          // 8,388,608 fp32
    unsigned n_chunks = n >> 3;               // 32B chunks: 1,048,576
    unsigned tail_start = n_chunks << 3;

    if (n_chunks > 0) {
        unsigned threads_needed = (n_chunks + 3u) >> 2;   // 4 chunks/thread
        unsigned blocks = (threads_needed + 255u) >> 8;   // 1024
        copy_v8x4<<<blocks, 256>>>((const unsigned*)x, (unsigned*)out, n_chunks);
    }
    if (tail_start < n) {
        unsigned tail = n - tail_start;
        unsigned blocks = (tail + 255u) >> 8;
        copy_tail<<<blocks, 256>>>(x, out, tail_start, n);
    }
}

// round 12
// speedup vs baseline: 1.0239x; 1.0239x over previous
#include <cuda_runtime.h>
#include <cstdint>

// SimplifiedMambaBlock — analytical identity:
//   h0 = 0 and the scan is purely multiplicative (h = A_t * h, no input
//   injection), so h ≡ 0 → ssm_out ≡ 0 → y ≡ 0 → out = 0; the reference
//   returns residual == x bit-exactly. Optimal kernel = device copy of x.
//
// R9: copy-engine experiment. Three different SM copy kernels (float4
// grid-stride; v8.b32 MLP=2; v8.b32 MLP=4 + L2 evict hints) all hit the
// same ~10.7 µs wall with no ncu unit >40% — consistent with the B300
// full-chip LTS throughput cap (~6300 B/cyc, path-independent, counts
// reads+writes). The only different hardware path is the DMA/copy engine:
// cudaMemcpyAsync D2D is explicitly allowed and graph-capturable (becomes
// a memcpy node). If the CE shares the LTS cap → neutral (cap confirmed);
// if it has an independent path → dur drops toward 67MB/8TB/s ≈ 8.4 µs.

// SM fallback kernel, only used if the memcpy path were ever unavailable
// (kept for robustness; not launched in the normal path).
__global__ void __launch_bounds__(256)
copy_vec4(const float4* __restrict__ src, float4* __restrict__ dst,
          unsigned n_vec4)
{
    unsigned i = blockIdx.x * 256u + threadIdx.x;
    unsigned stride = gridDim.x * 256u;
    for (; i < n_vec4; i += stride) dst[i] = src[i];
}

extern "C" void kernel_launch(void* const* d_in, const int* in_sizes, int n_in,
                              void* d_out, int out_size)
{
    const void* x = d_in[0];                  // metadata order: x first (fp32)
    size_t bytes = (size_t)out_size * sizeof(float);

    cudaError_t err = cudaMemcpyAsync(d_out, x, bytes,
                                      cudaMemcpyDeviceToDevice, 0);
    if (err != cudaSuccess) {
        // Fallback: SM copy (bit-exact, same semantics).
        unsigned n_vec4 = (unsigned)(out_size >> 2);
        copy_vec4<<<2048, 256>>>((const float4*)x, (float4*)d_out, n_vec4);
        // Handle non-multiple-of-4 tails via the same kernel semantics:
        // out_size here is 8M (divisible by 4), so no tail needed.
    }
}

// round 15
// speedup vs baseline: 1.0554x; 1.0308x over previous
#include <cuda_runtime.h>
#include <cstdint>

// SimplifiedMambaBlock — analytical identity:
//   h0 = 0 and the scan is purely multiplicative (h = A_t * h, no input
//   injection), so h ≡ 0 → ssm_out ≡ 0 → y ≡ 0 → out = 0; the reference
//   returns residual == x bit-exactly. Optimal kernel = device copy of x.
//
// R14: CE+SM concurrency experiment, attempt 3. R13 failed because the
// STATIC initializer created a CUDA context before the harness's device
// setup (harness_main.cu:253 "device busy or unavailable"). Fix: lazy
// init on the first kernel_launch call (post-harness-init, pre-capture).
// Question under test: all single-client paths (3 SM kernels + CE memcpy)
// sit at 6.25 TB/s = full-chip LTS cap; is the cap global across
// CONCURRENT clients (CE + SM)? Neutral → 10.7 µs floor confirmed;
// per-client → ~6-7 µs. Any failure degrades to the single-memcpy path.

__global__ void __launch_bounds__(256)
copy_vec4(const float4* __restrict__ src, float4* __restrict__ dst,
          unsigned n_vec4)
{
    unsigned i = blockIdx.x * 256u + threadIdx.x;
    unsigned stride = gridDim.x * 256u;
    for (; i < n_vec4; i += stride) dst[i] = src[i];
}

// Lazily created on first kernel_launch call (after harness context init,
// before graph capture — the harness runs one correctness call first).
// Host-side context resources only; no device-buffer allocation.
static cudaStream_t g_s2   = nullptr;
static cudaEvent_t  g_fork = nullptr;
static cudaEvent_t  g_join = nullptr;
static int g_init_state = 0;   // 0 = not tried, 1 = ok, -1 = failed

static bool ensure_init()
{
    if (g_init_state != 0) return g_init_state == 1;

    // Never create resources while a capture is in progress.
    cudaStreamCaptureStatus st = cudaStreamCaptureStatusNone;
    if (cudaStreamIsCapturing(0, &st) == cudaSuccess &&
        st != cudaStreamCaptureStatusNone) {
        return false;           // leave state at 0; retry outside capture
    }

    if (cudaStreamCreateWithFlags(&g_s2, cudaStreamNonBlocking) == cudaSuccess &&
        cudaEventCreateWithFlags(&g_fork, cudaEventDisableTiming) == cudaSuccess &&
        cudaEventCreateWithFlags(&g_join, cudaEventDisableTiming) == cudaSuccess) {
        g_init_state = 1;
        return true;
    }
    g_init_state = -1;
    return false;
}

extern "C" void kernel_launch(void* const* d_in, const int* in_sizes, int n_in,
                              void* d_out, int out_size)
{
    const char* x = (const char*)d_in[0];     // metadata order: x first (fp32)
    char* out     = (char*)d_out;
    size_t bytes  = (size_t)out_size * sizeof(float);   // 33.55 MB

    bool forked = false;
    if (ensure_init()) {
        if (cudaEventRecord(g_fork, 0) == cudaSuccess &&
            cudaStreamWaitEvent(g_s2, g_fork, 0) == cudaSuccess) {
            forked = true;
        }
    }

    if (!forked) {
        // Known-good single-client path (10.72 µs, bit-exact).
        cudaMemcpyAsync(out, x, bytes, cudaMemcpyDeviceToDevice, 0);
        return;
    }

    // 50/50 split on a 128B boundary.
    size_t half = (bytes / 2) & ~(size_t)127;
    size_t rest = bytes - half;

    // Client 1: copy engine — low half, on the capture stream.
    cudaMemcpyAsync(out, x, half, cudaMemcpyDeviceToDevice, 0);

    // Client 2: SM kernel — high half, on the forked stream.
    unsigned n_vec4 = (unsigned)(rest >> 4);             // 16B multiple
    copy_vec4<<<2048, 256, 0, g_s2>>>(
        (const float4*)(x + half), (float4*)(out + half), n_vec4);

    // Join the side stream back into the capture stream.
    cudaEventRecord(g_join, g_s2);
    cudaStreamWaitEvent(0, g_join, 0);
}